// round 1
// baseline (speedup 1.0000x reference)
#include <cuda_runtime.h>
#include <math.h>

// ---------------- static problem config ----------------
#define BN      960          // windows (B * WN)
#define P       144          // tokens per window
#define DIM     192
#define HEADS   6
#define DH      32
#define WT      64           // window types (MZ*MH)
#define MW      15
#define PSQ     (P * P)      // 20736
#define M_TOT   (BN * P)     // 138240
#define QKV_N   (3 * DIM)    // 576
#define SCALE   0.1767766952966369f  // 32^-0.5

// ---------------- scratch (device globals, no allocation) ----------------
// qkv laid out as [part][bn][head][p][dh]
__device__ float g_qkv[(size_t)3 * BN * HEADS * P * DH];     // ~318 MB
__device__ float g_attn[(size_t)M_TOT * DIM];                // ~106 MB
__device__ float g_bias[(size_t)WT * HEADS * PSQ];           // ~32 MB

// ---------------- kernel 0: densify earth-position bias ----------------
// g_bias[wt][h][i][j] = bias_table[pos(i,j)*WT*HEADS + wt*HEADS + h]
__global__ void bias_prep(const float* __restrict__ table) {
    const int wt = blockIdx.x;
    const int base_wt = wt * HEADS;
    for (int ij = threadIdx.x; ij < PSQ; ij += blockDim.x) {
        const int i = ij / P, j = ij % P;
        const int zi = i / 72, hi = (i / 12) % 6, wi = i % 12;
        const int zj = j / 72, hj = (j / 12) % 6, wj = j % 12;
        const int pos = (zi + 2 * zj) * 828 + (hi + 6 * hj) * 23 + (wi - wj + 11);
        const float* src = table + (size_t)pos * (WT * HEADS) + base_wt;
#pragma unroll
        for (int h = 0; h < HEADS; h++)
            g_bias[((size_t)(base_wt + h)) * PSQ + ij] = src[h];
    }
}

// ---------------- kernel 1: QKV GEMM ----------------
// C[M_TOT, 576] = X[M_TOT,192] @ Wqkv[192,576]; scatter into g_qkv layout,
// scale applied to the Q part.
__global__ void __launch_bounds__(256) gemm_qkv(const float* __restrict__ X,
                                                const float* __restrict__ W) {
    __shared__ __align__(16) float As[64][20];   // [m][k], padded: float4-aligned rows
    __shared__ __align__(16) float Bs[16][68];   // [k][n]
    const int bm = blockIdx.y * 64, bn = blockIdx.x * 64;
    const int tid = threadIdx.x;
    const int tx = tid & 15, ty = tid >> 4;
    float acc[4][4] = {};

    for (int kk = 0; kk < 192; kk += 16) {
        {
            const int am = tid >> 2, ak = (tid & 3) << 2;
            float4 v = *(const float4*)(X + (size_t)(bm + am) * 192 + kk + ak);
            *(float4*)&As[am][ak] = v;
        }
        {
            const int bk = tid >> 4, bn4 = (tid & 15) << 2;
            float4 v = *(const float4*)(W + (size_t)(kk + bk) * QKV_N + bn + bn4);
            *(float4*)&Bs[bk][bn4] = v;
        }
        __syncthreads();
#pragma unroll
        for (int kq = 0; kq < 4; kq++) {
            float a[4][4], b[4][4];
#pragma unroll
            for (int i = 0; i < 4; i++)
                *(float4*)a[i] = *(const float4*)&As[ty * 4 + i][kq * 4];
#pragma unroll
            for (int k = 0; k < 4; k++)
                *(float4*)b[k] = *(const float4*)&Bs[kq * 4 + k][tx * 4];
#pragma unroll
            for (int k = 0; k < 4; k++)
#pragma unroll
                for (int i = 0; i < 4; i++)
#pragma unroll
                    for (int j = 0; j < 4; j++)
                        acc[i][j] += a[i][k] * b[k][j];
        }
        __syncthreads();
    }

#pragma unroll
    for (int i = 0; i < 4; i++) {
        const int m = bm + ty * 4 + i;
        const int b_ = m / P, p = m % P;
#pragma unroll
        for (int j = 0; j < 4; j++) {
            const int n = bn + tx * 4 + j;
            const int part = n / DIM;
            const int hd = n % DIM;
            const int h = hd >> 5, d = hd & 31;
            float val = acc[i][j];
            if (part == 0) val *= SCALE;
            g_qkv[((((size_t)part * BN + b_) * HEADS + h) * P + p) * DH + d] = val;
        }
    }
}

// ---------------- kernel 2: per-(window, head) attention ----------------
__global__ void __launch_bounds__(256, 1) attn_kernel(const float* __restrict__ mask) {
    extern __shared__ float sm[];
    float* qs = sm;                  // [144][33]
    float* ks = qs + 144 * 33;       // [144][33]
    float* vs = ks + 144 * 33;       // [144][34]  (34: float2-aligned)
    float* ss = vs + 144 * 34;       // [144][145]

    const int bh = blockIdx.x;
    const int bn = bh / HEADS, h = bh % HEADS;
    const int wt = bn / MW;
    const int tid = threadIdx.x;

    const size_t hp = (size_t)P * DH;                       // 4608
    const size_t plane = (size_t)BN * HEADS * hp;
    const size_t qbase = ((size_t)bn * HEADS + h) * hp;
    // load q/k/v tiles
    for (int idx = tid; idx < P * DH; idx += 256) {
        const int p = idx >> 5, d = idx & 31;
        qs[p * 33 + d] = g_qkv[qbase + idx];
        ks[p * 33 + d] = g_qkv[plane + qbase + idx];
        vs[p * 34 + d] = g_qkv[2 * plane + qbase + idx];
    }
    __syncthreads();

    // ---- S = q @ k^T  (16x16 threads, 9x9 per thread) ----
    const int tx = tid & 15, ty = tid >> 4;
    const int r0 = ty * 9, c0 = tx * 9;
    float acc[9][9] = {};
#pragma unroll
    for (int k = 0; k < DH; k++) {
        float a[9], b[9];
#pragma unroll
        for (int i = 0; i < 9; i++) a[i] = qs[(r0 + i) * 33 + k];
#pragma unroll
        for (int j = 0; j < 9; j++) b[j] = ks[(c0 + j) * 33 + k];
#pragma unroll
        for (int i = 0; i < 9; i++)
#pragma unroll
            for (int j = 0; j < 9; j++)
                acc[i][j] += a[i] * b[j];
    }

    // ---- + bias + mask, write to ss ----
    const float* gb = g_bias + ((size_t)(wt * HEADS + h)) * PSQ;
    const float* mk = mask + (size_t)bn * PSQ;
#pragma unroll
    for (int i = 0; i < 9; i++) {
        const int row = r0 + i;
#pragma unroll
        for (int j = 0; j < 9; j++) {
            const int ij = row * P + c0 + j;
            ss[row * 145 + c0 + j] = acc[i][j] + gb[ij] + mk[ij];
        }
    }
    __syncthreads();

    // ---- softmax over rows (warp per row, 8 warps stride) ----
    const int warp = tid >> 5, lane = tid & 31;
    for (int i = warp; i < P; i += 8) {
        float* row = ss + i * 145;
        float m = -1e30f;
        for (int j = lane; j < P; j += 32) m = fmaxf(m, row[j]);
#pragma unroll
        for (int o = 16; o; o >>= 1) m = fmaxf(m, __shfl_xor_sync(0xffffffffu, m, o));
        float s = 0.f;
        for (int j = lane; j < P; j += 32) {
            const float e = expf(row[j] - m);
            row[j] = e;
            s += e;
        }
#pragma unroll
        for (int o = 16; o; o >>= 1) s += __shfl_xor_sync(0xffffffffu, s, o);
        const float inv = 1.f / s;
        for (int j = lane; j < P; j += 32) row[j] *= inv;
    }
    __syncthreads();

    // ---- O = S @ V  (9 rows x 2 cols per thread) ----
    const int rb = (tid >> 4) * 9;
    const int c = (tid & 15) * 2;
    float o0[9] = {}, o1[9] = {};
    for (int k = 0; k < P; k++) {
        const float2 v2 = *(const float2*)&vs[k * 34 + c];
#pragma unroll
        for (int i = 0; i < 9; i++) {
            const float s = ss[(rb + i) * 145 + k];
            o0[i] += s * v2.x;
            o1[i] += s * v2.y;
        }
    }
#pragma unroll
    for (int i = 0; i < 9; i++) {
        float2 r;
        r.x = o0[i];
        r.y = o1[i];
        *(float2*)&g_attn[((size_t)(bn * P + rb + i)) * DIM + h * 32 + c] = r;
    }
}

// ---------------- kernel 3: output projection + bias ----------------
__global__ void __launch_bounds__(256) gemm_proj(const float* __restrict__ W,
                                                 const float* __restrict__ bias,
                                                 float* __restrict__ out) {
    __shared__ __align__(16) float As[64][20];
    __shared__ __align__(16) float Bs[16][68];
    const int bm = blockIdx.y * 64, bn = blockIdx.x * 64;
    const int tid = threadIdx.x;
    const int tx = tid & 15, ty = tid >> 4;
    float acc[4][4] = {};

    for (int kk = 0; kk < 192; kk += 16) {
        {
            const int am = tid >> 2, ak = (tid & 3) << 2;
            float4 v = *(const float4*)(g_attn + (size_t)(bm + am) * 192 + kk + ak);
            *(float4*)&As[am][ak] = v;
        }
        {
            const int bk = tid >> 4, bn4 = (tid & 15) << 2;
            float4 v = *(const float4*)(W + (size_t)(kk + bk) * DIM + bn + bn4);
            *(float4*)&Bs[bk][bn4] = v;
        }
        __syncthreads();
#pragma unroll
        for (int kq = 0; kq < 4; kq++) {
            float a[4][4], b[4][4];
#pragma unroll
            for (int i = 0; i < 4; i++)
                *(float4*)a[i] = *(const float4*)&As[ty * 4 + i][kq * 4];
#pragma unroll
            for (int k = 0; k < 4; k++)
                *(float4*)b[k] = *(const float4*)&Bs[kq * 4 + k][tx * 4];
#pragma unroll
            for (int k = 0; k < 4; k++)
#pragma unroll
                for (int i = 0; i < 4; i++)
#pragma unroll
                    for (int j = 0; j < 4; j++)
                        acc[i][j] += a[i][k] * b[k][j];
        }
        __syncthreads();
    }

#pragma unroll
    for (int i = 0; i < 4; i++) {
        const int m = bm + ty * 4 + i;
#pragma unroll
        for (int j = 0; j < 4; j++) {
            const int n = bn + tx * 4 + j;
            out[(size_t)m * DIM + n] = acc[i][j] + bias[n];
        }
    }
}

// ---------------- launcher ----------------
extern "C" void kernel_launch(void* const* d_in, const int* in_sizes, int n_in,
                              void* d_out, int out_size) {
    const float* x          = (const float*)d_in[0];
    const float* mask       = (const float*)d_in[1];
    const float* w_qkv      = (const float*)d_in[2];
    const float* w_proj     = (const float*)d_in[3];
    const float* b_proj     = (const float*)d_in[4];
    const float* bias_table = (const float*)d_in[5];
    float* out = (float*)d_out;

    const int smem_attn = (144 * 33 + 144 * 33 + 144 * 34 + 144 * 145) * 4; // 141120 B
    cudaFuncSetAttribute(attn_kernel, cudaFuncAttributeMaxDynamicSharedMemorySize,
                         smem_attn);

    bias_prep<<<WT, 256>>>(bias_table);
    gemm_qkv<<<dim3(QKV_N / 64, M_TOT / 64), 256>>>(x, w_qkv);
    attn_kernel<<<BN * HEADS, 256, smem_attn>>>(mask);
    gemm_proj<<<dim3(DIM / 64, M_TOT / 64), 256>>>(w_proj, b_proj, out);
}

// round 2
// speedup vs baseline: 1.6662x; 1.6662x over previous
#include <cuda_runtime.h>
#include <math.h>

// ---------------- static problem config ----------------
#define BN      960
#define P       144
#define DIM     192
#define HEADS   6
#define DH      32
#define WT      64
#define MW      15
#define PSQ     (P * P)
#define M_TOT   (BN * P)          // 138240
#define QKV_N   (3 * DIM)         // 576
#define SCALE   0.1767766952966369f

// ---------------- scratch ----------------
__device__ float g_qkv[(size_t)3 * BN * HEADS * P * DH];
__device__ float g_attn[(size_t)M_TOT * DIM];
__device__ float g_bias[(size_t)WT * HEADS * PSQ];

// ---------------- helpers ----------------
__device__ __forceinline__ float cvt_tf32(float x) {
    unsigned u;
    asm("cvt.rna.tf32.f32 %0, %1;" : "=r"(u) : "f"(x));
    return __uint_as_float(u);
}
__device__ __forceinline__ unsigned fbits(float x) { return __float_as_uint(x); }

__device__ __forceinline__ void mma_tf32(float c[4], const unsigned a[4], const unsigned b[2]) {
    asm volatile(
        "mma.sync.aligned.m16n8k8.row.col.f32.tf32.tf32.f32 "
        "{%0,%1,%2,%3}, {%4,%5,%6,%7}, {%8,%9}, {%0,%1,%2,%3};"
        : "+f"(c[0]), "+f"(c[1]), "+f"(c[2]), "+f"(c[3])
        : "r"(a[0]), "r"(a[1]), "r"(a[2]), "r"(a[3]), "r"(b[0]), "r"(b[1]));
}

// ---------------- kernel 0: densify bias ----------------
__global__ void bias_prep(const float* __restrict__ table) {
    const int wt = blockIdx.x;
    const int base_wt = wt * HEADS;
    for (int ij = threadIdx.x; ij < PSQ; ij += blockDim.x) {
        const int i = ij / P, j = ij % P;
        const int zi = i / 72, hi = (i / 12) % 6, wi = i % 12;
        const int zj = j / 72, hj = (j / 12) % 6, wj = j % 12;
        const int pos = (zi + 2 * zj) * 828 + (hi + 6 * hj) * 23 + (wi - wj + 11);
        const float* src = table + (size_t)pos * (WT * HEADS) + base_wt;
#pragma unroll
        for (int h = 0; h < HEADS; h++)
            g_bias[((size_t)(base_wt + h)) * PSQ + ij] = src[h];
    }
}

// ---------------- tf32 mma GEMM: C[M,NCOLS] = X[M,192] @ W[192,NCOLS] ----------------
// block tile 128x64, 8 warps of 32x32. IS_QKV: scatter epilogue into g_qkv (+scale Q).
// else: out = C + bias.
template<int NCOLS, bool IS_QKV>
__global__ void __launch_bounds__(256) gemm_mma(const float* __restrict__ Xin,
                                                const float* __restrict__ W,
                                                const float* __restrict__ bias,
                                                float* __restrict__ out) {
    __shared__ __align__(16) float As[128][36];   // stride 36: frag bank = 4g+t (perm)
    __shared__ __align__(16) float Bs[32][72];    // stride 72: frag bank = 8t+g (perm)
    const float* X = IS_QKV ? Xin : g_attn;

    const int bm = blockIdx.y * 128, bn = blockIdx.x * 64;
    const int tid = threadIdx.x;
    const int w = tid >> 5, lane = tid & 31;
    const int g = lane >> 2, t = lane & 3;
    const int wm = w & 3, wn = w >> 2;          // 4x2 warp grid
    const int m0 = wm * 32, n0 = wn * 32;

    float cc[2][4][4] = {};
    float4 ra[4], rb[2];

    // initial global fetch (k0 = 0)
#pragma unroll
    for (int i = 0; i < 4; i++) {
        const int r = (tid >> 3) + 32 * i, c = (tid & 7) * 4;
        ra[i] = *(const float4*)(X + (size_t)(bm + r) * 192 + c);
    }
#pragma unroll
    for (int i = 0; i < 2; i++) {
        const int r = (tid >> 4) + 16 * i, c = (tid & 15) * 4;
        rb[i] = *(const float4*)(W + (size_t)r * NCOLS + bn + c);
    }

    for (int k0 = 0; k0 < 192; k0 += 32) {
        __syncthreads();
        // store stage (tf32-rounded)
#pragma unroll
        for (int i = 0; i < 4; i++) {
            const int r = (tid >> 3) + 32 * i, c = (tid & 7) * 4;
            float4 v = ra[i];
            As[r][c + 0] = cvt_tf32(v.x); As[r][c + 1] = cvt_tf32(v.y);
            As[r][c + 2] = cvt_tf32(v.z); As[r][c + 3] = cvt_tf32(v.w);
        }
#pragma unroll
        for (int i = 0; i < 2; i++) {
            const int r = (tid >> 4) + 16 * i, c = (tid & 15) * 4;
            float4 v = rb[i];
            Bs[r][c + 0] = cvt_tf32(v.x); Bs[r][c + 1] = cvt_tf32(v.y);
            Bs[r][c + 2] = cvt_tf32(v.z); Bs[r][c + 3] = cvt_tf32(v.w);
        }
        __syncthreads();
        // prefetch next stage
        if (k0 + 32 < 192) {
#pragma unroll
            for (int i = 0; i < 4; i++) {
                const int r = (tid >> 3) + 32 * i, c = (tid & 7) * 4;
                ra[i] = *(const float4*)(X + (size_t)(bm + r) * 192 + k0 + 32 + c);
            }
#pragma unroll
            for (int i = 0; i < 2; i++) {
                const int r = (tid >> 4) + 16 * i, c = (tid & 15) * 4;
                rb[i] = *(const float4*)(W + (size_t)(k0 + 32 + r) * NCOLS + bn + c);
            }
        }
        // compute 4 x k8
#pragma unroll
        for (int kk = 0; kk < 32; kk += 8) {
            unsigned af[2][4], bf[4][2];
#pragma unroll
            for (int mt = 0; mt < 2; mt++) {
                const float* p = &As[m0 + mt * 16 + g][kk + t];
                af[mt][0] = fbits(p[0]);
                af[mt][1] = fbits(p[8 * 36]);
                af[mt][2] = fbits(p[4]);
                af[mt][3] = fbits(p[8 * 36 + 4]);
            }
#pragma unroll
            for (int nt = 0; nt < 4; nt++) {
                const float* p = &Bs[kk + t][n0 + nt * 8 + g];
                bf[nt][0] = fbits(p[0]);
                bf[nt][1] = fbits(p[4 * 72]);
            }
#pragma unroll
            for (int mt = 0; mt < 2; mt++)
#pragma unroll
                for (int nt = 0; nt < 4; nt++)
                    mma_tf32(cc[mt][nt], af[mt], bf[nt]);
        }
    }

    // epilogue
#pragma unroll
    for (int mt = 0; mt < 2; mt++) {
#pragma unroll
        for (int half = 0; half < 2; half++) {
            const int m = bm + m0 + mt * 16 + g + half * 8;
            if (IS_QKV) {
                const int b_ = m / P, p = m % P;
#pragma unroll
                for (int nt = 0; nt < 4; nt++) {
                    const int n = bn + n0 + nt * 8 + 2 * t;
                    const int part = n / DIM, cp = n % DIM;
                    const int h = cp >> 5, d = cp & 31;
                    float v0 = cc[mt][nt][half * 2 + 0];
                    float v1 = cc[mt][nt][half * 2 + 1];
                    if (part == 0) { v0 *= SCALE; v1 *= SCALE; }
                    float2 st; st.x = v0; st.y = v1;
                    *(float2*)(g_qkv + ((((size_t)part * BN + b_) * HEADS + h) * P + p) * DH + d) = st;
                }
            } else {
#pragma unroll
                for (int nt = 0; nt < 4; nt++) {
                    const int n = bn + n0 + nt * 8 + 2 * t;
                    float2 st;
                    st.x = cc[mt][nt][half * 2 + 0] + __ldg(bias + n);
                    st.y = cc[mt][nt][half * 2 + 1] + __ldg(bias + n + 1);
                    *(float2*)(out + (size_t)m * DIM + n) = st;
                }
            }
        }
    }
}

// ---------------- attention: one CTA (288 thr / 9 warps) per (window, head) ----------------
// smem (floats): qs[144][36], ks[144][36], vs[144][40], ss[144][148]
#define QS_OFF 0
#define KS_OFF (144 * 36)
#define VS_OFF (2 * 144 * 36)
#define SS_OFF (2 * 144 * 36 + 144 * 40)
#define ATTN_SMEM_FLOATS (2 * 144 * 36 + 144 * 40 + 144 * 148)

__global__ void __launch_bounds__(288, 1) attn_mma(const float* __restrict__ mask) {
    extern __shared__ float sm[];
    float* qs = sm + QS_OFF;
    float* ks = sm + KS_OFF;
    float* vs = sm + VS_OFF;
    float* ss = sm + SS_OFF;

    const int bh = blockIdx.x;
    const int bn = bh / HEADS, h = bh % HEADS;
    const int wt = bn / MW;
    const int tid = threadIdx.x;
    const int w = tid >> 5, lane = tid & 31;
    const int g = lane >> 2, t = lane & 3;

    const size_t hp = (size_t)P * DH;
    const size_t plane = (size_t)BN * HEADS * hp;
    const size_t qbase = ((size_t)bn * HEADS + h) * hp;

    // ---- stage q/k/v (tf32-rounded), float4 granular ----
    for (int f = tid; f < P * DH / 4; f += 288) {
        const int p = f >> 3, d = (f & 7) * 4;
        float4 q4 = *(const float4*)(g_qkv + qbase + f * 4);
        float4 k4 = *(const float4*)(g_qkv + plane + qbase + f * 4);
        float4 v4 = *(const float4*)(g_qkv + 2 * plane + qbase + f * 4);
        float* qp = qs + p * 36 + d;
        qp[0] = cvt_tf32(q4.x); qp[1] = cvt_tf32(q4.y); qp[2] = cvt_tf32(q4.z); qp[3] = cvt_tf32(q4.w);
        float* kp = ks + p * 36 + d;
        kp[0] = cvt_tf32(k4.x); kp[1] = cvt_tf32(k4.y); kp[2] = cvt_tf32(k4.z); kp[3] = cvt_tf32(k4.w);
        float* vp = vs + p * 40 + d;
        vp[0] = cvt_tf32(v4.x); vp[1] = cvt_tf32(v4.y); vp[2] = cvt_tf32(v4.z); vp[3] = cvt_tf32(v4.w);
    }

    // ---- prefill ss with bias + mask (coalesced float4) ----
    const float* gb = g_bias + ((size_t)(wt * HEADS + h)) * PSQ;
    const float* mk = mask + (size_t)bn * PSQ;
    for (int f = tid; f < PSQ / 4; f += 288) {
        const int i = f / 36, jc = (f % 36) * 4;
        float4 b4 = *(const float4*)(gb + i * P + jc);
        float4 m4 = *(const float4*)(mk + i * P + jc);
        float4 r; r.x = b4.x + m4.x; r.y = b4.y + m4.y; r.z = b4.z + m4.z; r.w = b4.w + m4.w;
        *(float4*)(ss + i * 148 + jc) = r;
    }
    __syncthreads();

    // ---- S = Q @ K^T : warp tile 48x48 (3x3 warp grid) ----
    {
        const int wr = (w / 3) * 48, wc = (w % 3) * 48;
        float cc[3][6][4] = {};
#pragma unroll
        for (int kk = 0; kk < DH; kk += 8) {
            unsigned af[3][4], bf[6][2];
#pragma unroll
            for (int mt = 0; mt < 3; mt++) {
                const float* p = qs + (wr + mt * 16 + g) * 36 + kk + t;
                af[mt][0] = fbits(p[0]);
                af[mt][1] = fbits(p[8 * 36]);
                af[mt][2] = fbits(p[4]);
                af[mt][3] = fbits(p[8 * 36 + 4]);
            }
#pragma unroll
            for (int nt = 0; nt < 6; nt++) {
                const float* p = ks + (wc + nt * 8 + g) * 36 + kk + t;
                bf[nt][0] = fbits(p[0]);
                bf[nt][1] = fbits(p[4]);
            }
#pragma unroll
            for (int mt = 0; mt < 3; mt++)
#pragma unroll
                for (int nt = 0; nt < 6; nt++)
                    mma_tf32(cc[mt][nt], af[mt], bf[nt]);
        }
        // accumulate into ss (which holds bias+mask)
#pragma unroll
        for (int mt = 0; mt < 3; mt++) {
#pragma unroll
            for (int nt = 0; nt < 6; nt++) {
                float* p0 = ss + (wr + mt * 16 + g) * 148 + wc + nt * 8 + 2 * t;
                float2 v0 = *(float2*)p0;
                v0.x += cc[mt][nt][0]; v0.y += cc[mt][nt][1];
                *(float2*)p0 = v0;
                float* p1 = p0 + 8 * 148;
                float2 v1 = *(float2*)p1;
                v1.x += cc[mt][nt][2]; v1.y += cc[mt][nt][3];
                *(float2*)p1 = v1;
            }
        }
    }
    __syncthreads();

    // ---- softmax (warp per row, 9-warp stride), tf32-round the probs ----
    for (int i = w; i < P; i += 9) {
        float* row = ss + i * 148;
        float m = -1e30f;
        for (int j = lane; j < P; j += 32) m = fmaxf(m, row[j]);
#pragma unroll
        for (int o = 16; o; o >>= 1) m = fmaxf(m, __shfl_xor_sync(0xffffffffu, m, o));
        float s = 0.f;
        for (int j = lane; j < P; j += 32) {
            const float e = __expf(row[j] - m);
            row[j] = e;
            s += e;
        }
#pragma unroll
        for (int o = 16; o; o >>= 1) s += __shfl_xor_sync(0xffffffffu, s, o);
        const float inv = 1.f / s;
        for (int j = lane; j < P; j += 32) row[j] = cvt_tf32(row[j] * inv);
    }
    __syncthreads();

    // ---- O = S @ V : warp handles 16 rows x 32 cols ----
    {
        const int wr = w * 16;
        float cc[4][4] = {};
        for (int k0 = 0; k0 < P; k0 += 8) {
            unsigned af[4], bf[4][2];
            const float* ap = ss + (wr + g) * 148 + k0 + t;
            af[0] = fbits(ap[0]);
            af[1] = fbits(ap[8 * 148]);
            af[2] = fbits(ap[4]);
            af[3] = fbits(ap[8 * 148 + 4]);
#pragma unroll
            for (int nt = 0; nt < 4; nt++) {
                const float* p = vs + (k0 + t) * 40 + nt * 8 + g;
                bf[nt][0] = fbits(p[0]);
                bf[nt][1] = fbits(p[4 * 40]);
            }
#pragma unroll
            for (int nt = 0; nt < 4; nt++)
                mma_tf32(cc[nt], af, bf[nt]);
        }
        // store to g_attn[(bn*P + row)*DIM + h*32 + col]
        const size_t obase = ((size_t)bn * P) * DIM + h * 32;
#pragma unroll
        for (int nt = 0; nt < 4; nt++) {
            const int col = nt * 8 + 2 * t;
            float2 s0; s0.x = cc[nt][0]; s0.y = cc[nt][1];
            *(float2*)(g_attn + obase + (size_t)(wr + g) * DIM + col) = s0;
            float2 s1; s1.x = cc[nt][2]; s1.y = cc[nt][3];
            *(float2*)(g_attn + obase + (size_t)(wr + g + 8) * DIM + col) = s1;
        }
    }
}

// ---------------- launcher ----------------
extern "C" void kernel_launch(void* const* d_in, const int* in_sizes, int n_in,
                              void* d_out, int out_size) {
    const float* x          = (const float*)d_in[0];
    const float* mask       = (const float*)d_in[1];
    const float* w_qkv      = (const float*)d_in[2];
    const float* w_proj     = (const float*)d_in[3];
    const float* b_proj     = (const float*)d_in[4];
    const float* bias_table = (const float*)d_in[5];
    float* out = (float*)d_out;

    const int smem_attn = ATTN_SMEM_FLOATS * 4;  // 149760 B
    cudaFuncSetAttribute(attn_mma, cudaFuncAttributeMaxDynamicSharedMemorySize, smem_attn);

    bias_prep<<<WT, 256>>>(bias_table);
    gemm_mma<QKV_N, true><<<dim3(QKV_N / 64, M_TOT / 128), 256>>>(x, w_qkv, nullptr, nullptr);
    attn_mma<<<BN * HEADS, 288, smem_attn>>>(mask);
    gemm_mma<DIM, false><<<dim3(DIM / 64, M_TOT / 128), 256>>>(nullptr, w_proj, b_proj, out);
}

// round 3
// speedup vs baseline: 3.0673x; 1.8408x over previous
#include <cuda_runtime.h>
#include <math.h>

// ---------------- static problem config ----------------
#define BN      960
#define P       144
#define DIM     192
#define HEADS   6
#define DH      32
#define WT      64
#define MW      15
#define PSQ     (P * P)
#define M_TOT   (BN * P)          // 138240
#define QKV_N   (3 * DIM)         // 576
#define SCALE   0.1767766952966369f

// ---------------- scratch ----------------
__device__ float g_qkv[(size_t)3 * BN * HEADS * P * DH];
__device__ float g_attn[(size_t)M_TOT * DIM];
__device__ float g_bias[(size_t)WT * HEADS * PSQ];

// ---------------- helpers ----------------
__device__ __forceinline__ float cvt_tf32(float x) {
    unsigned u;
    asm("cvt.rna.tf32.f32 %0, %1;" : "=r"(u) : "f"(x));
    return __uint_as_float(u);
}
__device__ __forceinline__ unsigned fbits(float x) { return __float_as_uint(x); }
__device__ __forceinline__ unsigned tb(float x) { // tf32 bits (rna) from f32
    unsigned u;
    asm("cvt.rna.tf32.f32 %0, %1;" : "=r"(u) : "f"(x));
    return u;
}

__device__ __forceinline__ void mma_tf32(float c[4], const unsigned a[4], const unsigned b[2]) {
    asm volatile(
        "mma.sync.aligned.m16n8k8.row.col.f32.tf32.tf32.f32 "
        "{%0,%1,%2,%3}, {%4,%5,%6,%7}, {%8,%9}, {%0,%1,%2,%3};"
        : "+f"(c[0]), "+f"(c[1]), "+f"(c[2]), "+f"(c[3])
        : "r"(a[0]), "r"(a[1]), "r"(a[2]), "r"(a[3]), "r"(b[0]), "r"(b[1]));
}

__device__ __forceinline__ void cp_async16(void* smem, const void* gmem) {
    unsigned s = (unsigned)__cvta_generic_to_shared(smem);
    asm volatile("cp.async.ca.shared.global [%0], [%1], 16;" :: "r"(s), "l"(gmem));
}
#define CP_COMMIT() asm volatile("cp.async.commit_group;")
template<int N> __device__ __forceinline__ void cp_wait() {
    asm volatile("cp.async.wait_group %0;" :: "n"(N));
}

// ---------------- kernel 0: densify bias ----------------
__global__ void bias_prep(const float* __restrict__ table) {
    const int wt = blockIdx.x;
    const int base_wt = wt * HEADS;
    for (int ij = threadIdx.x; ij < PSQ; ij += blockDim.x) {
        const int i = ij / P, j = ij % P;
        const int zi = i / 72, hi = (i / 12) % 6, wi = i % 12;
        const int zj = j / 72, hj = (j / 12) % 6, wj = j % 12;
        const int pos = (zi + 2 * zj) * 828 + (hi + 6 * hj) * 23 + (wi - wj + 11);
        const float* src = table + (size_t)pos * (WT * HEADS) + base_wt;
#pragma unroll
        for (int h = 0; h < HEADS; h++)
            g_bias[((size_t)(base_wt + h)) * PSQ + ij] = src[h];
    }
}

// ---------------- tf32 mma GEMM with cp.async double buffer ----------------
// C[M,NCOLS] = X[M,192] @ W[192,NCOLS]; block 128x64, 8 warps of 32x32.
template<int NCOLS, bool IS_QKV>
__global__ void __launch_bounds__(256) gemm_mma(const float* __restrict__ Xin,
                                                const float* __restrict__ W,
                                                const float* __restrict__ bias,
                                                float* __restrict__ out) {
    extern __shared__ float smem[];
    float* As = smem;               // [2][128*36]
    float* Bs = smem + 2 * 128 * 36; // [2][32*72]
    const float* X = IS_QKV ? Xin : g_attn;

    const int bm = blockIdx.y * 128, bn = blockIdx.x * 64;
    const int tid = threadIdx.x;
    const int w = tid >> 5, lane = tid & 31;
    const int g = lane >> 2, t = lane & 3;
    const int wm = w & 3, wn = w >> 2;
    const int m0 = wm * 32, n0 = wn * 32;

    float cc[2][4][4] = {};

#define ISSUE_TILE(buf, k0)                                                        \
    {                                                                              \
        float* Ab = As + (buf) * 128 * 36;                                         \
        _Pragma("unroll")                                                          \
        for (int i = 0; i < 4; i++) {                                              \
            const int r = (tid >> 3) + 32 * i, c = (tid & 7) * 4;                  \
            cp_async16(Ab + r * 36 + c, X + (size_t)(bm + r) * 192 + (k0) + c);    \
        }                                                                          \
        float* Bb = Bs + (buf) * 32 * 72;                                          \
        _Pragma("unroll")                                                          \
        for (int i = 0; i < 2; i++) {                                              \
            const int r = (tid >> 4) + 16 * i, c = (tid & 15) * 4;                 \
            cp_async16(Bb + r * 72 + c, W + (size_t)((k0) + r) * NCOLS + bn + c);  \
        }                                                                          \
    }

    ISSUE_TILE(0, 0);
    CP_COMMIT();

#pragma unroll
    for (int it = 0; it < 6; ++it) {
        if (it < 5) {
            ISSUE_TILE((it + 1) & 1, 32 * (it + 1));
            CP_COMMIT();
            cp_wait<1>();
        } else {
            cp_wait<0>();
        }
        __syncthreads();
        const float* Ab = As + (it & 1) * 128 * 36;
        const float* Bb = Bs + (it & 1) * 32 * 72;
#pragma unroll
        for (int kk = 0; kk < 32; kk += 8) {
            unsigned af[2][4], bf[4][2];
#pragma unroll
            for (int mt = 0; mt < 2; mt++) {
                const float* p = Ab + (m0 + mt * 16 + g) * 36 + kk + t;
                af[mt][0] = tb(p[0]);
                af[mt][1] = tb(p[8 * 36]);
                af[mt][2] = tb(p[4]);
                af[mt][3] = tb(p[8 * 36 + 4]);
            }
#pragma unroll
            for (int nt = 0; nt < 4; nt++) {
                const float* p = Bb + (kk + t) * 72 + n0 + nt * 8 + g;
                bf[nt][0] = tb(p[0]);
                bf[nt][1] = tb(p[4 * 72]);
            }
#pragma unroll
            for (int mt = 0; mt < 2; mt++)
#pragma unroll
                for (int nt = 0; nt < 4; nt++)
                    mma_tf32(cc[mt][nt], af[mt], bf[nt]);
        }
        __syncthreads();
    }
#undef ISSUE_TILE

    // epilogue
#pragma unroll
    for (int mt = 0; mt < 2; mt++) {
#pragma unroll
        for (int half = 0; half < 2; half++) {
            const int m = bm + m0 + mt * 16 + g + half * 8;
            if (IS_QKV) {
                const int b_ = m / P, p = m % P;
#pragma unroll
                for (int nt = 0; nt < 4; nt++) {
                    const int n = bn + n0 + nt * 8 + 2 * t;
                    const int part = n / DIM, cp = n % DIM;
                    const int h = cp >> 5, d = cp & 31;
                    float v0 = cc[mt][nt][half * 2 + 0];
                    float v1 = cc[mt][nt][half * 2 + 1];
                    if (part == 0) { v0 *= SCALE; v1 *= SCALE; }
                    float2 st; st.x = v0; st.y = v1;
                    *(float2*)(g_qkv + ((((size_t)part * BN + b_) * HEADS + h) * P + p) * DH + d) = st;
                }
            } else {
#pragma unroll
                for (int nt = 0; nt < 4; nt++) {
                    const int n = bn + n0 + nt * 8 + 2 * t;
                    float2 st;
                    st.x = cc[mt][nt][half * 2 + 0] + __ldg(bias + n);
                    st.y = cc[mt][nt][half * 2 + 1] + __ldg(bias + n + 1);
                    *(float2*)(out + (size_t)m * DIM + n) = st;
                }
            }
        }
    }
}

// ---------------- attention: warp-local, register softmax ----------------
// smem: qs[144][36], ks[144][36], vs[144][40] = 64512 B. 9 warps, warp w owns
// rows [16w, 16w+16). One syncthreads total.
#define ATTN_SMEM_BYTES ((2 * 144 * 36 + 144 * 40) * 4)

__global__ void __launch_bounds__(288, 2) attn_mma(const float* __restrict__ mask) {
    extern __shared__ float sm[];
    float* qs = sm;
    float* ks = sm + 144 * 36;
    float* vs = sm + 2 * 144 * 36;

    const int bh = blockIdx.x;
    const int bn = bh / HEADS, h = bh % HEADS;
    const int wt = bn / MW;
    const int tid = threadIdx.x;
    const int w = tid >> 5, lane = tid & 31;
    const int g = lane >> 2, t = lane & 3;

    const size_t hp = (size_t)P * DH;
    const size_t plane = (size_t)BN * HEADS * hp;
    const size_t qbase = ((size_t)bn * HEADS + h) * hp;

    // ---- stage q/k/v (tf32-rounded) ----
    for (int f = tid; f < P * DH / 4; f += 288) {
        const int p = f >> 3, d = (f & 7) * 4;
        float4 q4 = *(const float4*)(g_qkv + qbase + f * 4);
        float4 k4 = *(const float4*)(g_qkv + plane + qbase + f * 4);
        float4 v4 = *(const float4*)(g_qkv + 2 * plane + qbase + f * 4);
        float* qp = qs + p * 36 + d;
        qp[0] = cvt_tf32(q4.x); qp[1] = cvt_tf32(q4.y); qp[2] = cvt_tf32(q4.z); qp[3] = cvt_tf32(q4.w);
        float* kp = ks + p * 36 + d;
        kp[0] = cvt_tf32(k4.x); kp[1] = cvt_tf32(k4.y); kp[2] = cvt_tf32(k4.z); kp[3] = cvt_tf32(k4.w);
        float* vp = vs + p * 40 + d;
        vp[0] = cvt_tf32(v4.x); vp[1] = cvt_tf32(v4.y); vp[2] = cvt_tf32(v4.z); vp[3] = cvt_tf32(v4.w);
    }
    __syncthreads();

    const int wr = w * 16;

    // ---- S = Q @ K^T : 18 m16n8 tiles, accum in regs ----
    float s[18][4] = {};
#pragma unroll
    for (int kk = 0; kk < DH; kk += 8) {
        unsigned af[4];
        const float* ap = qs + (wr + g) * 36 + kk + t;
        af[0] = fbits(ap[0]);
        af[1] = fbits(ap[8 * 36]);
        af[2] = fbits(ap[4]);
        af[3] = fbits(ap[8 * 36 + 4]);
#pragma unroll
        for (int nt = 0; nt < 18; nt++) {
            unsigned bf[2];
            const float* bp = ks + (nt * 8 + g) * 36 + kk + t;
            bf[0] = fbits(bp[0]);
            bf[1] = fbits(bp[4]);
            mma_tf32(s[nt], af, bf);
        }
    }

    // ---- + bias + mask (direct into fragments) ----
    {
        const float* gb = g_bias + ((size_t)(wt * HEADS + h)) * PSQ;
        const float* mk = mask + (size_t)bn * PSQ;
        const int r0 = wr + g, r1 = r0 + 8;
#pragma unroll
        for (int nt = 0; nt < 18; nt++) {
            const int c = nt * 8 + 2 * t;
            float2 b0 = *(const float2*)(gb + (size_t)r0 * P + c);
            float2 m0 = *(const float2*)(mk + (size_t)r0 * P + c);
            float2 b1 = *(const float2*)(gb + (size_t)r1 * P + c);
            float2 m1 = *(const float2*)(mk + (size_t)r1 * P + c);
            s[nt][0] += b0.x + m0.x;
            s[nt][1] += b0.y + m0.y;
            s[nt][2] += b1.x + m1.x;
            s[nt][3] += b1.y + m1.y;
        }
    }

    // ---- softmax in registers (rows r0 = wr+g, r1 = wr+g+8) ----
    {
        float mx0 = -1e30f, mx1 = -1e30f;
#pragma unroll
        for (int nt = 0; nt < 18; nt++) {
            mx0 = fmaxf(mx0, fmaxf(s[nt][0], s[nt][1]));
            mx1 = fmaxf(mx1, fmaxf(s[nt][2], s[nt][3]));
        }
        mx0 = fmaxf(mx0, __shfl_xor_sync(0xffffffffu, mx0, 1));
        mx0 = fmaxf(mx0, __shfl_xor_sync(0xffffffffu, mx0, 2));
        mx1 = fmaxf(mx1, __shfl_xor_sync(0xffffffffu, mx1, 1));
        mx1 = fmaxf(mx1, __shfl_xor_sync(0xffffffffu, mx1, 2));
        float s0 = 0.f, s1 = 0.f;
#pragma unroll
        for (int nt = 0; nt < 18; nt++) {
            s[nt][0] = __expf(s[nt][0] - mx0);
            s[nt][1] = __expf(s[nt][1] - mx0);
            s[nt][2] = __expf(s[nt][2] - mx1);
            s[nt][3] = __expf(s[nt][3] - mx1);
            s0 += s[nt][0] + s[nt][1];
            s1 += s[nt][2] + s[nt][3];
        }
        s0 += __shfl_xor_sync(0xffffffffu, s0, 1);
        s0 += __shfl_xor_sync(0xffffffffu, s0, 2);
        s1 += __shfl_xor_sync(0xffffffffu, s1, 1);
        s1 += __shfl_xor_sync(0xffffffffu, s1, 2);
        const float i0 = 1.f / s0, i1 = 1.f / s1;
#pragma unroll
        for (int nt = 0; nt < 18; nt++) {
            s[nt][0] = cvt_tf32(s[nt][0] * i0);
            s[nt][1] = cvt_tf32(s[nt][1] * i0);
            s[nt][2] = cvt_tf32(s[nt][2] * i1);
            s[nt][3] = cvt_tf32(s[nt][3] * i1);
        }
    }

    // ---- O = S @ V : C-frag -> A-frag via shuffles, no smem, no sync ----
    {
        float o[4][4] = {};
        const int src1 = (g << 2) | (t >> 1);
        const int src2 = src1 + 2;
        const bool odd = (t & 1);
#pragma unroll
        for (int kb = 0; kb < 18; kb++) {
            float x0 = __shfl_sync(0xffffffffu, s[kb][0], src1);
            float y0 = __shfl_sync(0xffffffffu, s[kb][1], src1);
            float x1 = __shfl_sync(0xffffffffu, s[kb][2], src1);
            float y1 = __shfl_sync(0xffffffffu, s[kb][3], src1);
            float x2 = __shfl_sync(0xffffffffu, s[kb][0], src2);
            float y2 = __shfl_sync(0xffffffffu, s[kb][1], src2);
            float x3 = __shfl_sync(0xffffffffu, s[kb][2], src2);
            float y3 = __shfl_sync(0xffffffffu, s[kb][3], src2);
            unsigned a[4];
            a[0] = fbits(odd ? y0 : x0);  // A[g][t]
            a[1] = fbits(odd ? y1 : x1);  // A[g+8][t]
            a[2] = fbits(odd ? y2 : x2);  // A[g][t+4]
            a[3] = fbits(odd ? y3 : x3);  // A[g+8][t+4]
#pragma unroll
            for (int nt = 0; nt < 4; nt++) {
                unsigned bf[2];
                const float* vp = vs + (kb * 8 + t) * 40 + nt * 8 + g;
                bf[0] = fbits(vp[0]);
                bf[1] = fbits(vp[4 * 40]);
                mma_tf32(o[nt], a, bf);
            }
        }
        const size_t obase = ((size_t)bn * P) * DIM + h * 32;
#pragma unroll
        for (int nt = 0; nt < 4; nt++) {
            const int col = nt * 8 + 2 * t;
            float2 s0v; s0v.x = o[nt][0]; s0v.y = o[nt][1];
            *(float2*)(g_attn + obase + (size_t)(wr + g) * DIM + col) = s0v;
            float2 s1v; s1v.x = o[nt][2]; s1v.y = o[nt][3];
            *(float2*)(g_attn + obase + (size_t)(wr + g + 8) * DIM + col) = s1v;
        }
    }
}

// ---------------- launcher ----------------
extern "C" void kernel_launch(void* const* d_in, const int* in_sizes, int n_in,
                              void* d_out, int out_size) {
    const float* x          = (const float*)d_in[0];
    const float* mask       = (const float*)d_in[1];
    const float* w_qkv      = (const float*)d_in[2];
    const float* w_proj     = (const float*)d_in[3];
    const float* b_proj     = (const float*)d_in[4];
    const float* bias_table = (const float*)d_in[5];
    float* out = (float*)d_out;

    const int smem_gemm = (2 * 128 * 36 + 2 * 32 * 72) * 4;   // 55296 B
    cudaFuncSetAttribute(gemm_mma<QKV_N, true>,
                         cudaFuncAttributeMaxDynamicSharedMemorySize, smem_gemm);
    cudaFuncSetAttribute(gemm_mma<DIM, false>,
                         cudaFuncAttributeMaxDynamicSharedMemorySize, smem_gemm);
    cudaFuncSetAttribute(attn_mma,
                         cudaFuncAttributeMaxDynamicSharedMemorySize, ATTN_SMEM_BYTES);

    bias_prep<<<WT, 256>>>(bias_table);
    gemm_mma<QKV_N, true><<<dim3(QKV_N / 64, M_TOT / 128), 256, smem_gemm>>>(x, w_qkv, nullptr, nullptr);
    attn_mma<<<BN * HEADS, 288, ATTN_SMEM_BYTES>>>(mask);
    gemm_mma<DIM, false><<<dim3(DIM / 64, M_TOT / 128), 256, smem_gemm>>>(nullptr, w_proj, b_proj, out);
}

// round 4
// speedup vs baseline: 4.0105x; 1.3075x over previous
#include <cuda_runtime.h>
#include <cuda_fp16.h>
#include <math.h>

// ---------------- static problem config ----------------
#define BN      960
#define P       144
#define DIM     192
#define HEADS   6
#define DH      32
#define WT      64
#define MW      15
#define PSQ     (P * P)
#define M_TOT   (BN * P)          // 138240
#define SCALE   0.1767766952966369f

// ---------------- scratch (uint-typed for alignment; 2 halfs per uint) -----
__device__ unsigned g_qkv_h[(size_t)3 * BN * HEADS * P * DH / 2];   // 159 MB
__device__ unsigned g_xo_h[(size_t)M_TOT * DIM / 2];                // 53 MB (x_h, later attn-out)
__device__ unsigned g_wq_h[576 * 192 / 2];
__device__ unsigned g_wp_h[192 * 192 / 2];
__device__ float    g_bias[(size_t)WT * HEADS * PSQ];               // 32 MB

// ---------------- helpers ----------------
__device__ __forceinline__ unsigned ph2(float a, float b) {
    __half2 h = __floats2half2_rn(make_float2(a, b).x, make_float2(a, b).y);
    return *(unsigned*)&h;
}
__device__ __forceinline__ void mma_f16(float c[4], const unsigned a[4], const unsigned b[2]) {
    asm volatile(
        "mma.sync.aligned.m16n8k16.row.col.f32.f16.f16.f32 "
        "{%0,%1,%2,%3}, {%4,%5,%6,%7}, {%8,%9}, {%0,%1,%2,%3};"
        : "+f"(c[0]), "+f"(c[1]), "+f"(c[2]), "+f"(c[3])
        : "r"(a[0]), "r"(a[1]), "r"(a[2]), "r"(a[3]), "r"(b[0]), "r"(b[1]));
}
__device__ __forceinline__ void cp_async16(void* smem, const void* gmem) {
    unsigned s = (unsigned)__cvta_generic_to_shared(smem);
    asm volatile("cp.async.ca.shared.global [%0], [%1], 16;" :: "r"(s), "l"(gmem));
}
#define CP_COMMIT() asm volatile("cp.async.commit_group;")
template<int N> __device__ __forceinline__ void cp_wait() {
    asm volatile("cp.async.wait_group %0;" :: "n"(N));
}

// ---------------- prep: x -> half ----------------
__global__ void conv_x(const float* __restrict__ x) {
    const int i = blockIdx.x * blockDim.x + threadIdx.x;   // float4 index
    if (i >= M_TOT * DIM / 4) return;
    float4 v = ((const float4*)x)[i];
    uint2 o;
    o.x = ph2(v.x, v.y);
    o.y = ph2(v.z, v.w);
    ((uint2*)g_xo_h)[i] = o;
}

// ---------------- prep: weights -> half, transposed to [n][k] ----------------
__global__ void conv_w(const float* __restrict__ wq, const float* __restrict__ wp) {
    const int stride = gridDim.x * blockDim.x;
    int gid = blockIdx.x * blockDim.x + threadIdx.x;
    for (int i = gid; i < 576 * 96; i += stride) {        // pairs along k
        const int n = i / 96, k = (i % 96) * 2;
        g_wq_h[n * 96 + (k >> 1)] = ph2(wq[(size_t)k * 576 + n], wq[(size_t)(k + 1) * 576 + n]);
    }
    for (int i = gid; i < 192 * 96; i += stride) {
        const int n = i / 96, k = (i % 96) * 2;
        g_wp_h[n * 96 + (k >> 1)] = ph2(wp[(size_t)k * 192 + n], wp[(size_t)(k + 1) * 192 + n]);
    }
}

// ---------------- prep: densify bias (512 blocks) ----------------
__global__ void bias_prep(const float* __restrict__ table) {
    const int wt = blockIdx.x >> 3, chunk = blockIdx.x & 7;
    const int base_wt = wt * HEADS;
    const int lo = chunk * (PSQ / 8), hi = lo + PSQ / 8;
    for (int ij = lo + threadIdx.x; ij < hi; ij += blockDim.x) {
        const int i = ij / P, j = ij % P;
        const int zi = i / 72, hi_ = (i / 12) % 6, wi = i % 12;
        const int zj = j / 72, hj = (j / 12) % 6, wj = j % 12;
        const int pos = (zi + 2 * zj) * 828 + (hi_ + 6 * hj) * 23 + (wi - wj + 11);
        const float* src = table + (size_t)pos * (WT * HEADS) + base_wt;
#pragma unroll
        for (int h = 0; h < HEADS; h++)
            g_bias[((size_t)(base_wt + h)) * PSQ + ij] = src[h];
    }
}

// ---------------- fp16 mma GEMM ----------------
// C[M,*] = X[M,192] @ W^T; X = g_xo_h (halfs, [m][192]); W = [n][192] halfs.
// block 128x64, 8 warps (4x2) of 32x32, k-slab 64, double buffered cp.async.
template<bool IS_QKV>
__global__ void __launch_bounds__(256) gemm_h(const float* __restrict__ bias,
                                              float* __restrict__ out) {
    extern __shared__ __half smh[];
    __half* As = smh;                    // [2][128*72]
    __half* Bs = smh + 2 * 128 * 72;     // [2][64*72]
    const __half* X = (const __half*)g_xo_h;
    const __half* W = IS_QKV ? (const __half*)g_wq_h : (const __half*)g_wp_h;

    const int bm = blockIdx.y * 128, bn = blockIdx.x * 64;
    const int tid = threadIdx.x;
    const int w = tid >> 5, lane = tid & 31;
    const int g = lane >> 2, t = lane & 3;
    const int m0 = (w & 3) * 32, n0 = (w >> 2) * 32;

    float cc[2][4][4] = {};

#define ISSUE_TILE(buf, k0)                                                       \
    {                                                                             \
        __half* Ab = As + (buf) * 128 * 72;                                       \
        _Pragma("unroll")                                                         \
        for (int i = 0; i < 4; i++) {                                             \
            const int idx = tid + 256 * i;                                        \
            const int r = idx >> 3, c = (idx & 7) * 8;                            \
            cp_async16(Ab + r * 72 + c, X + (size_t)(bm + r) * 192 + (k0) + c);   \
        }                                                                         \
        __half* Bb = Bs + (buf) * 64 * 72;                                        \
        _Pragma("unroll")                                                         \
        for (int i = 0; i < 2; i++) {                                             \
            const int idx = tid + 256 * i;                                        \
            const int r = idx >> 3, c = (idx & 7) * 8;                            \
            cp_async16(Bb + r * 72 + c, W + (size_t)(bn + r) * 192 + (k0) + c);   \
        }                                                                         \
    }

    ISSUE_TILE(0, 0);
    CP_COMMIT();

#pragma unroll
    for (int it = 0; it < 3; ++it) {
        if (it < 2) {
            ISSUE_TILE((it + 1) & 1, 64 * (it + 1));
            CP_COMMIT();
            cp_wait<1>();
        } else {
            cp_wait<0>();
        }
        __syncthreads();
        const __half* Ab = As + (it & 1) * 128 * 72;
        const __half* Bb = Bs + (it & 1) * 64 * 72;
#pragma unroll
        for (int kk = 0; kk < 64; kk += 16) {
            unsigned af[2][4], bf[4][2];
#pragma unroll
            for (int mt = 0; mt < 2; mt++) {
                const __half* p = Ab + (m0 + mt * 16 + g) * 72 + kk + 2 * t;
                af[mt][0] = *(const unsigned*)p;
                af[mt][1] = *(const unsigned*)(p + 8 * 72);
                af[mt][2] = *(const unsigned*)(p + 8);
                af[mt][3] = *(const unsigned*)(p + 8 * 72 + 8);
            }
#pragma unroll
            for (int nt = 0; nt < 4; nt++) {
                const __half* p = Bb + (n0 + nt * 8 + g) * 72 + kk + 2 * t;
                bf[nt][0] = *(const unsigned*)p;
                bf[nt][1] = *(const unsigned*)(p + 8);
            }
#pragma unroll
            for (int mt = 0; mt < 2; mt++)
#pragma unroll
                for (int nt = 0; nt < 4; nt++)
                    mma_f16(cc[mt][nt], af[mt], bf[nt]);
        }
        __syncthreads();
    }
#undef ISSUE_TILE

    // epilogue
#pragma unroll
    for (int mt = 0; mt < 2; mt++) {
#pragma unroll
        for (int half_ = 0; half_ < 2; half_++) {
            const int m = bm + m0 + mt * 16 + g + half_ * 8;
            if (IS_QKV) {
                const int b_ = m / P, p = m % P;
#pragma unroll
                for (int nt = 0; nt < 4; nt++) {
                    const int n = bn + n0 + nt * 8 + 2 * t;
                    const int part = n / DIM, cp = n % DIM;
                    const int h = cp >> 5, d = cp & 31;
                    float v0 = cc[mt][nt][half_ * 2 + 0];
                    float v1 = cc[mt][nt][half_ * 2 + 1];
                    if (part == 0) { v0 *= SCALE; v1 *= SCALE; }
                    const size_t di = ((((size_t)part * BN + b_) * HEADS + h) * P + p) * DH + d;
                    *(unsigned*)((__half*)g_qkv_h + di) = ph2(v0, v1);
                }
            } else {
#pragma unroll
                for (int nt = 0; nt < 4; nt++) {
                    const int n = bn + n0 + nt * 8 + 2 * t;
                    float2 st;
                    st.x = cc[mt][nt][half_ * 2 + 0] + __ldg(bias + n);
                    st.y = cc[mt][nt][half_ * 2 + 1] + __ldg(bias + n + 1);
                    *(float2*)(out + (size_t)m * DIM + n) = st;
                }
            }
        }
    }
}

// ---------------- attention: fp16 mma, warp-local, zero-shuffle AV ----------------
__global__ void __launch_bounds__(288, 2) attn_h(const float* __restrict__ mask) {
    __shared__ __align__(16) __half qs[144 * 40];
    __shared__ __align__(16) __half ks[144 * 40];
    __shared__ __align__(16) __half vT[32 * 152];

    const int bh = blockIdx.x;
    const int bn = bh / HEADS, h = bh % HEADS;
    const int wt = bn / MW;
    const int tid = threadIdx.x;
    const int w = tid >> 5, lane = tid & 31;
    const int g = lane >> 2, t = lane & 3;

    const size_t hp = (size_t)P * DH;                 // 4608 halfs
    const size_t plane = (size_t)BN * HEADS * hp;
    const size_t qbase = ((size_t)bn * HEADS + h) * hp;
    const __half* gq = (const __half*)g_qkv_h + qbase;
    const __half* gk = (const __half*)g_qkv_h + plane + qbase;
    const __half* gv = (const __half*)g_qkv_h + 2 * plane + qbase;

    // stage q/k (8 halfs per chunk)
    for (int f = tid; f < 576; f += 288) {
        const int p = f >> 2, c = (f & 3) * 8;
        *(uint4*)(qs + p * 40 + c) = *(const uint4*)(gq + p * 32 + c);
        *(uint4*)(ks + p * 40 + c) = *(const uint4*)(gk + p * 32 + c);
    }
    // stage v transposed: vT[d][p]
    for (int f = tid; f < 2304; f += 288) {
        const int p = f >> 4, d = (f & 15) * 2;
        __half2 v2 = *(const __half2*)(gv + p * 32 + d);
        vT[d * 152 + p] = __low2half(v2);
        vT[(d + 1) * 152 + p] = __high2half(v2);
    }
    __syncthreads();

    const int wr = w * 16;

    // ---- S = Q @ K^T : 18 tiles, 2 k16 slices ----
    float s[18][4] = {};
#pragma unroll
    for (int kk = 0; kk < DH; kk += 16) {
        unsigned af[4];
        const __half* ap = qs + (wr + g) * 40 + kk + 2 * t;
        af[0] = *(const unsigned*)ap;
        af[1] = *(const unsigned*)(ap + 8 * 40);
        af[2] = *(const unsigned*)(ap + 8);
        af[3] = *(const unsigned*)(ap + 8 * 40 + 8);
#pragma unroll
        for (int nt = 0; nt < 18; nt++) {
            unsigned bf[2];
            const __half* bp = ks + (nt * 8 + g) * 40 + kk + 2 * t;
            bf[0] = *(const unsigned*)bp;
            bf[1] = *(const unsigned*)(bp + 8);
            mma_f16(s[nt], af, bf);
        }
    }

    // ---- + bias + mask ----
    {
        const float* gb = g_bias + ((size_t)(wt * HEADS + h)) * PSQ;
        const float* mk = mask + (size_t)bn * PSQ;
        const int r0 = wr + g, r1 = r0 + 8;
#pragma unroll
        for (int nt = 0; nt < 18; nt++) {
            const int c = nt * 8 + 2 * t;
            float2 b0 = *(const float2*)(gb + (size_t)r0 * P + c);
            float2 m0 = *(const float2*)(mk + (size_t)r0 * P + c);
            float2 b1 = *(const float2*)(gb + (size_t)r1 * P + c);
            float2 m1 = *(const float2*)(mk + (size_t)r1 * P + c);
            s[nt][0] += b0.x + m0.x;
            s[nt][1] += b0.y + m0.y;
            s[nt][2] += b1.x + m1.x;
            s[nt][3] += b1.y + m1.y;
        }
    }

    // ---- softmax in registers ----
    {
        float mx0 = -1e30f, mx1 = -1e30f;
#pragma unroll
        for (int nt = 0; nt < 18; nt++) {
            mx0 = fmaxf(mx0, fmaxf(s[nt][0], s[nt][1]));
            mx1 = fmaxf(mx1, fmaxf(s[nt][2], s[nt][3]));
        }
        mx0 = fmaxf(mx0, __shfl_xor_sync(0xffffffffu, mx0, 1));
        mx0 = fmaxf(mx0, __shfl_xor_sync(0xffffffffu, mx0, 2));
        mx1 = fmaxf(mx1, __shfl_xor_sync(0xffffffffu, mx1, 1));
        mx1 = fmaxf(mx1, __shfl_xor_sync(0xffffffffu, mx1, 2));
        float s0 = 0.f, s1 = 0.f;
#pragma unroll
        for (int nt = 0; nt < 18; nt++) {
            s[nt][0] = __expf(s[nt][0] - mx0);
            s[nt][1] = __expf(s[nt][1] - mx0);
            s[nt][2] = __expf(s[nt][2] - mx1);
            s[nt][3] = __expf(s[nt][3] - mx1);
            s0 += s[nt][0] + s[nt][1];
            s1 += s[nt][2] + s[nt][3];
        }
        s0 += __shfl_xor_sync(0xffffffffu, s0, 1);
        s0 += __shfl_xor_sync(0xffffffffu, s0, 2);
        s1 += __shfl_xor_sync(0xffffffffu, s1, 1);
        s1 += __shfl_xor_sync(0xffffffffu, s1, 2);
        const float i0 = 1.f / s0, i1 = 1.f / s1;
#pragma unroll
        for (int nt = 0; nt < 18; nt++) {
            s[nt][0] *= i0; s[nt][1] *= i0;
            s[nt][2] *= i1; s[nt][3] *= i1;
        }
    }

    // ---- O = S @ V : C-frag == A-frag layout (no shuffles) ----
    {
        float o[4][4] = {};
#pragma unroll
        for (int kb = 0; kb < 9; kb++) {
            unsigned a[4];
            a[0] = ph2(s[2 * kb][0], s[2 * kb][1]);
            a[1] = ph2(s[2 * kb][2], s[2 * kb][3]);
            a[2] = ph2(s[2 * kb + 1][0], s[2 * kb + 1][1]);
            a[3] = ph2(s[2 * kb + 1][2], s[2 * kb + 1][3]);
#pragma unroll
            for (int nt = 0; nt < 4; nt++) {
                unsigned bf[2];
                const __half* bp = vT + (nt * 8 + g) * 152 + kb * 16 + 2 * t;
                bf[0] = *(const unsigned*)bp;
                bf[1] = *(const unsigned*)(bp + 8);
                mma_f16(o[nt], a, bf);
            }
        }
        __half* go = (__half*)g_xo_h + ((size_t)bn * P) * DIM + h * 32;
#pragma unroll
        for (int nt = 0; nt < 4; nt++) {
            const int col = nt * 8 + 2 * t;
            *(unsigned*)(go + (size_t)(wr + g) * DIM + col)     = ph2(o[nt][0], o[nt][1]);
            *(unsigned*)(go + (size_t)(wr + g + 8) * DIM + col) = ph2(o[nt][2], o[nt][3]);
        }
    }
}

// ---------------- launcher ----------------
extern "C" void kernel_launch(void* const* d_in, const int* in_sizes, int n_in,
                              void* d_out, int out_size) {
    const float* x          = (const float*)d_in[0];
    const float* mask       = (const float*)d_in[1];
    const float* w_qkv      = (const float*)d_in[2];
    const float* w_proj     = (const float*)d_in[3];
    const float* b_proj     = (const float*)d_in[4];
    const float* bias_table = (const float*)d_in[5];
    float* out = (float*)d_out;

    const int smem_gemm = (2 * 128 * 72 + 2 * 64 * 72) * 2;   // 55296 B
    cudaFuncSetAttribute(gemm_h<true>,
                         cudaFuncAttributeMaxDynamicSharedMemorySize, smem_gemm);
    cudaFuncSetAttribute(gemm_h<false>,
                         cudaFuncAttributeMaxDynamicSharedMemorySize, smem_gemm);

    conv_x<<<(M_TOT * DIM / 4 + 255) / 256, 256>>>(x);
    conv_w<<<128, 256>>>(w_qkv, w_proj);
    bias_prep<<<WT * 8, 256>>>(bias_table);
    gemm_h<true><<<dim3(9, M_TOT / 128), 256, smem_gemm>>>(nullptr, nullptr);
    attn_h<<<BN * HEADS, 288>>>(mask);
    gemm_h<false><<<dim3(3, M_TOT / 128), 256, smem_gemm>>>(b_proj, out);
}

// round 5
// speedup vs baseline: 5.0668x; 1.2634x over previous
#include <cuda_runtime.h>
#include <cuda_fp16.h>
#include <math.h>

// ---------------- static problem config ----------------
#define BN      960
#define P       144
#define DIM     192
#define HEADS   6
#define DH      32
#define WT      64
#define MW      15
#define PSQ     (P * P)
#define M_TOT   (BN * P)          // 138240
#define SCALE   0.1767766952966369f
#define LOG2E   1.4426950408889634f

// ---------------- scratch ----------------
__device__ unsigned g_qkv_h[(size_t)3 * BN * HEADS * P * DH / 2];   // 159 MB
__device__ unsigned g_xo_h[(size_t)M_TOT * DIM / 2];                // 53 MB
__device__ unsigned g_wq_h[576 * 192 / 2];
__device__ unsigned g_wp_h[192 * 192 / 2];
__device__ unsigned g_bias_h[(size_t)WT * HEADS * PSQ / 2];         // 16 MB
__device__ unsigned g_mask_h[(size_t)BN * PSQ / 2];                 // 40 MB

// ---------------- helpers ----------------
__device__ __forceinline__ unsigned ph2(float a, float b) {
    __half2 h = __floats2half2_rn(a, b);
    return *(unsigned*)&h;
}
__device__ __forceinline__ float ex2(float x) {
    float y;
    asm("ex2.approx.f32 %0, %1;" : "=f"(y) : "f"(x));
    return y;
}
__device__ __forceinline__ void mma_f16(float c[4], const unsigned a[4], const unsigned b[2]) {
    asm volatile(
        "mma.sync.aligned.m16n8k16.row.col.f32.f16.f16.f32 "
        "{%0,%1,%2,%3}, {%4,%5,%6,%7}, {%8,%9}, {%0,%1,%2,%3};"
        : "+f"(c[0]), "+f"(c[1]), "+f"(c[2]), "+f"(c[3])
        : "r"(a[0]), "r"(a[1]), "r"(a[2]), "r"(a[3]), "r"(b[0]), "r"(b[1]));
}
__device__ __forceinline__ void ldsm4(unsigned r[4], unsigned saddr) {
    asm volatile("ldmatrix.sync.aligned.m8n8.x4.shared.b16 {%0,%1,%2,%3}, [%4];"
                 : "=r"(r[0]), "=r"(r[1]), "=r"(r[2]), "=r"(r[3]) : "r"(saddr));
}
__device__ __forceinline__ void cp_async16(void* smem, const void* gmem) {
    unsigned s = (unsigned)__cvta_generic_to_shared(smem);
    asm volatile("cp.async.ca.shared.global [%0], [%1], 16;" :: "r"(s), "l"(gmem));
}
#define CP_COMMIT() asm volatile("cp.async.commit_group;")
template<int N> __device__ __forceinline__ void cp_wait() {
    asm volatile("cp.async.wait_group %0;" :: "n"(N));
}

// ---------------- prep kernels ----------------
__global__ void conv_x(const float* __restrict__ x) {
    const int i = blockIdx.x * blockDim.x + threadIdx.x;
    if (i >= M_TOT * DIM / 4) return;
    float4 v = ((const float4*)x)[i];
    uint2 o;
    o.x = ph2(v.x, v.y);
    o.y = ph2(v.z, v.w);
    ((uint2*)g_xo_h)[i] = o;
}

__global__ void conv_mask(const float* __restrict__ mask) {
    const int i = blockIdx.x * blockDim.x + threadIdx.x;
    if (i >= BN * PSQ / 4) return;
    float4 v = ((const float4*)mask)[i];
    uint2 o;
    o.x = ph2(v.x * LOG2E, v.y * LOG2E);
    o.y = ph2(v.z * LOG2E, v.w * LOG2E);
    ((uint2*)g_mask_h)[i] = o;
}

__global__ void conv_w(const float* __restrict__ wq, const float* __restrict__ wp) {
    const int stride = gridDim.x * blockDim.x;
    int gid = blockIdx.x * blockDim.x + threadIdx.x;
    for (int i = gid; i < 576 * 96; i += stride) {
        const int n = i / 96, k = (i % 96) * 2;
        g_wq_h[n * 96 + (k >> 1)] = ph2(wq[(size_t)k * 576 + n], wq[(size_t)(k + 1) * 576 + n]);
    }
    for (int i = gid; i < 192 * 96; i += stride) {
        const int n = i / 96, k = (i % 96) * 2;
        g_wp_h[n * 96 + (k >> 1)] = ph2(wp[(size_t)k * 192 + n], wp[(size_t)(k + 1) * 192 + n]);
    }
}

__global__ void bias_prep(const float* __restrict__ table) {
    const int wt = blockIdx.x >> 3, chunk = blockIdx.x & 7;
    const int base_wt = wt * HEADS;
    const int lo = chunk * (PSQ / 8), hi = lo + PSQ / 8;
    __half* gb = (__half*)g_bias_h;
    for (int ij = lo + threadIdx.x; ij < hi; ij += blockDim.x) {
        const int i = ij / P, j = ij % P;
        const int zi = i / 72, hi_ = (i / 12) % 6, wi = i % 12;
        const int zj = j / 72, hj = (j / 12) % 6, wj = j % 12;
        const int pos = (zi + 2 * zj) * 828 + (hi_ + 6 * hj) * 23 + (wi - wj + 11);
        const float* src = table + (size_t)pos * (WT * HEADS) + base_wt;
#pragma unroll
        for (int h = 0; h < HEADS; h++)
            gb[((size_t)(base_wt + h)) * PSQ + ij] = __float2half(src[h] * LOG2E);
    }
}

// ---------------- fp16 mma GEMM (ldmatrix) ----------------
template<bool IS_QKV>
__global__ void __launch_bounds__(256) gemm_h(const float* __restrict__ bias,
                                              float* __restrict__ out) {
    extern __shared__ __half smh[];
    __half* As = smh;                    // [2][128*72]
    __half* Bs = smh + 2 * 128 * 72;     // [2][64*72]
    const __half* X = (const __half*)g_xo_h;
    const __half* W = IS_QKV ? (const __half*)g_wq_h : (const __half*)g_wp_h;

    const int bm = blockIdx.y * 128, bn = blockIdx.x * 64;
    const int tid = threadIdx.x;
    const int w = tid >> 5, lane = tid & 31;
    const int g = lane >> 2, t = lane & 3;
    const int m0 = (w & 3) * 32, n0 = (w >> 2) * 32;

    // ldmatrix lane geometry
    const int arow = m0 + (lane & 15);
    const int acol = (lane >> 4) * 8;
    const int brow = n0 + (lane >> 4) * 8 + (lane & 7);
    const int bcol = ((lane >> 3) & 1) * 8;

    float cc[2][4][4] = {};

#define ISSUE_TILE(buf, k0)                                                       \
    {                                                                             \
        __half* Ab = As + (buf) * 128 * 72;                                       \
        _Pragma("unroll")                                                         \
        for (int i = 0; i < 4; i++) {                                             \
            const int idx = tid + 256 * i;                                        \
            const int r = idx >> 3, c = (idx & 7) * 8;                            \
            cp_async16(Ab + r * 72 + c, X + (size_t)(bm + r) * 192 + (k0) + c);   \
        }                                                                         \
        __half* Bb = Bs + (buf) * 64 * 72;                                        \
        _Pragma("unroll")                                                         \
        for (int i = 0; i < 2; i++) {                                             \
            const int idx = tid + 256 * i;                                        \
            const int r = idx >> 3, c = (idx & 7) * 8;                            \
            cp_async16(Bb + r * 72 + c, W + (size_t)(bn + r) * 192 + (k0) + c);   \
        }                                                                         \
    }

    ISSUE_TILE(0, 0);
    CP_COMMIT();

#pragma unroll
    for (int it = 0; it < 3; ++it) {
        if (it < 2) {
            ISSUE_TILE((it + 1) & 1, 64 * (it + 1));
            CP_COMMIT();
            cp_wait<1>();
        } else {
            cp_wait<0>();
        }
        __syncthreads();
        const unsigned sA = (unsigned)__cvta_generic_to_shared(As + (it & 1) * 128 * 72);
        const unsigned sB = (unsigned)__cvta_generic_to_shared(Bs + (it & 1) * 64 * 72);
#pragma unroll
        for (int kk = 0; kk < 64; kk += 16) {
            unsigned af[2][4], bf[4][2];
#pragma unroll
            for (int mt = 0; mt < 2; mt++)
                ldsm4(af[mt], sA + ((arow + mt * 16) * 72 + kk + acol) * 2);
#pragma unroll
            for (int nt2 = 0; nt2 < 2; nt2++) {
                unsigned r[4];
                ldsm4(r, sB + ((brow + nt2 * 16) * 72 + kk + bcol) * 2);
                bf[nt2 * 2][0] = r[0]; bf[nt2 * 2][1] = r[1];
                bf[nt2 * 2 + 1][0] = r[2]; bf[nt2 * 2 + 1][1] = r[3];
            }
#pragma unroll
            for (int mt = 0; mt < 2; mt++)
#pragma unroll
                for (int nt = 0; nt < 4; nt++)
                    mma_f16(cc[mt][nt], af[mt], bf[nt]);
        }
        __syncthreads();
    }
#undef ISSUE_TILE

    // epilogue
#pragma unroll
    for (int mt = 0; mt < 2; mt++) {
#pragma unroll
        for (int half_ = 0; half_ < 2; half_++) {
            const int m = bm + m0 + mt * 16 + g + half_ * 8;
            if (IS_QKV) {
                const int b_ = m / P, p = m % P;
#pragma unroll
                for (int nt = 0; nt < 4; nt++) {
                    const int n = bn + n0 + nt * 8 + 2 * t;
                    const int part = n / DIM, cp = n % DIM;
                    const int h = cp >> 5, d = cp & 31;
                    float v0 = cc[mt][nt][half_ * 2 + 0];
                    float v1 = cc[mt][nt][half_ * 2 + 1];
                    if (part == 0) { v0 *= SCALE * LOG2E; v1 *= SCALE * LOG2E; }
                    const size_t di = ((((size_t)part * BN + b_) * HEADS + h) * P + p) * DH + d;
                    *(unsigned*)((__half*)g_qkv_h + di) = ph2(v0, v1);
                }
            } else {
#pragma unroll
                for (int nt = 0; nt < 4; nt++) {
                    const int n = bn + n0 + nt * 8 + 2 * t;
                    float2 st;
                    st.x = cc[mt][nt][half_ * 2 + 0] + __ldg(bias + n);
                    st.y = cc[mt][nt][half_ * 2 + 1] + __ldg(bias + n + 1);
                    *(float2*)(out + (size_t)m * DIM + n) = st;
                }
            }
        }
    }
}

// ---------------- attention ----------------
__global__ void __launch_bounds__(288, 2) attn_h(int dummy) {
    __shared__ __align__(16) __half qs[144 * 40];
    __shared__ __align__(16) __half ks[144 * 40];
    __shared__ __align__(16) __half vT[32 * 152];

    const int bh = blockIdx.x;
    const int bn = bh / HEADS, h = bh % HEADS;
    const int wt = bn / MW;
    const int tid = threadIdx.x;
    const int w = tid >> 5, lane = tid & 31;
    const int g = lane >> 2, t = lane & 3;

    const size_t hp = (size_t)P * DH;
    const size_t plane = (size_t)BN * HEADS * hp;
    const size_t qbase = ((size_t)bn * HEADS + h) * hp;
    const __half* gq = (const __half*)g_qkv_h + qbase;
    const __half* gk = (const __half*)g_qkv_h + plane + qbase;
    const __half* gv = (const __half*)g_qkv_h + 2 * plane + qbase;

    for (int f = tid; f < 576; f += 288) {
        const int p = f >> 2, c = (f & 3) * 8;
        *(uint4*)(qs + p * 40 + c) = *(const uint4*)(gq + p * 32 + c);
        *(uint4*)(ks + p * 40 + c) = *(const uint4*)(gk + p * 32 + c);
    }
    for (int f = tid; f < 2304; f += 288) {
        const int p = f >> 4, d = (f & 15) * 2;
        __half2 v2 = *(const __half2*)(gv + p * 32 + d);
        vT[d * 152 + p] = __low2half(v2);
        vT[(d + 1) * 152 + p] = __high2half(v2);
    }
    __syncthreads();

    const int wr = w * 16;
    const unsigned sQ = (unsigned)__cvta_generic_to_shared(qs);
    const unsigned sK = (unsigned)__cvta_generic_to_shared(ks);
    const unsigned sV = (unsigned)__cvta_generic_to_shared(vT);

    // ldmatrix lane geometry
    const int qrow = wr + (lane & 15);
    const int qcol = (lane >> 4) * 8;
    const int krow = (lane >> 4) * 8 + (lane & 7);
    const int kcol = ((lane >> 3) & 1) * 8;

    // ---- S = Q @ K^T ----
    float s[18][4] = {};
#pragma unroll
    for (int kk = 0; kk < DH; kk += 16) {
        unsigned af[4];
        ldsm4(af, sQ + (qrow * 40 + kk + qcol) * 2);
#pragma unroll
        for (int nt2 = 0; nt2 < 9; nt2++) {
            unsigned r[4];
            ldsm4(r, sK + ((krow + nt2 * 16) * 40 + kk + kcol) * 2);
            unsigned b0[2] = { r[0], r[1] };
            unsigned b1[2] = { r[2], r[3] };
            mma_f16(s[2 * nt2], af, b0);
            mma_f16(s[2 * nt2 + 1], af, b1);
        }
    }

    // ---- + bias + mask (fp16, pre-scaled by log2e) ----
    {
        const __half* gb = (const __half*)g_bias_h + ((size_t)(wt * HEADS + h)) * PSQ;
        const __half* mk = (const __half*)g_mask_h + (size_t)bn * PSQ;
        const int r0 = wr + g, r1 = r0 + 8;
#pragma unroll
        for (int nt = 0; nt < 18; nt++) {
            const int c = nt * 8 + 2 * t;
            __half2 a0 = __hadd2(*(const __half2*)(gb + (size_t)r0 * P + c),
                                 *(const __half2*)(mk + (size_t)r0 * P + c));
            __half2 a1 = __hadd2(*(const __half2*)(gb + (size_t)r1 * P + c),
                                 *(const __half2*)(mk + (size_t)r1 * P + c));
            float2 f0 = __half22float2(a0);
            float2 f1 = __half22float2(a1);
            s[nt][0] += f0.x; s[nt][1] += f0.y;
            s[nt][2] += f1.x; s[nt][3] += f1.y;
        }
    }

    // ---- softmax (base-2 domain) ----
    {
        float mx0 = -1e30f, mx1 = -1e30f;
#pragma unroll
        for (int nt = 0; nt < 18; nt++) {
            mx0 = fmaxf(mx0, fmaxf(s[nt][0], s[nt][1]));
            mx1 = fmaxf(mx1, fmaxf(s[nt][2], s[nt][3]));
        }
        mx0 = fmaxf(mx0, __shfl_xor_sync(0xffffffffu, mx0, 1));
        mx0 = fmaxf(mx0, __shfl_xor_sync(0xffffffffu, mx0, 2));
        mx1 = fmaxf(mx1, __shfl_xor_sync(0xffffffffu, mx1, 1));
        mx1 = fmaxf(mx1, __shfl_xor_sync(0xffffffffu, mx1, 2));
        float s0 = 0.f, s1 = 0.f;
#pragma unroll
        for (int nt = 0; nt < 18; nt++) {
            s[nt][0] = ex2(s[nt][0] - mx0);
            s[nt][1] = ex2(s[nt][1] - mx0);
            s[nt][2] = ex2(s[nt][2] - mx1);
            s[nt][3] = ex2(s[nt][3] - mx1);
            s0 += s[nt][0] + s[nt][1];
            s1 += s[nt][2] + s[nt][3];
        }
        s0 += __shfl_xor_sync(0xffffffffu, s0, 1);
        s0 += __shfl_xor_sync(0xffffffffu, s0, 2);
        s1 += __shfl_xor_sync(0xffffffffu, s1, 1);
        s1 += __shfl_xor_sync(0xffffffffu, s1, 2);
        const float i0 = 1.f / s0, i1 = 1.f / s1;
#pragma unroll
        for (int nt = 0; nt < 18; nt++) {
            s[nt][0] *= i0; s[nt][1] *= i0;
            s[nt][2] *= i1; s[nt][3] *= i1;
        }
    }

    // ---- O = S @ V (C-frag == A-frag) ----
    {
        float o[4][4] = {};
        const int vrow = (lane >> 4) * 8 + (lane & 7);
        const int vcol = ((lane >> 3) & 1) * 8;
#pragma unroll
        for (int kb = 0; kb < 9; kb++) {
            unsigned a[4];
            a[0] = ph2(s[2 * kb][0], s[2 * kb][1]);
            a[1] = ph2(s[2 * kb][2], s[2 * kb][3]);
            a[2] = ph2(s[2 * kb + 1][0], s[2 * kb + 1][1]);
            a[3] = ph2(s[2 * kb + 1][2], s[2 * kb + 1][3]);
#pragma unroll
            for (int nt2 = 0; nt2 < 2; nt2++) {
                unsigned r[4];
                ldsm4(r, sV + ((vrow + nt2 * 16) * 152 + kb * 16 + vcol) * 2);
                unsigned b0[2] = { r[0], r[1] };
                unsigned b1[2] = { r[2], r[3] };
                mma_f16(o[nt2 * 2], a, b0);
                mma_f16(o[nt2 * 2 + 1], a, b1);
            }
        }
        __half* go = (__half*)g_xo_h + ((size_t)bn * P) * DIM + h * 32;
#pragma unroll
        for (int nt = 0; nt < 4; nt++) {
            const int col = nt * 8 + 2 * t;
            *(unsigned*)(go + (size_t)(wr + g) * DIM + col)     = ph2(o[nt][0], o[nt][1]);
            *(unsigned*)(go + (size_t)(wr + g + 8) * DIM + col) = ph2(o[nt][2], o[nt][3]);
        }
    }
}

// ---------------- launcher ----------------
extern "C" void kernel_launch(void* const* d_in, const int* in_sizes, int n_in,
                              void* d_out, int out_size) {
    const float* x          = (const float*)d_in[0];
    const float* mask       = (const float*)d_in[1];
    const float* w_qkv      = (const float*)d_in[2];
    const float* w_proj     = (const float*)d_in[3];
    const float* b_proj     = (const float*)d_in[4];
    const float* bias_table = (const float*)d_in[5];
    float* out = (float*)d_out;

    const int smem_gemm = (2 * 128 * 72 + 2 * 64 * 72) * 2;   // 55296 B
    cudaFuncSetAttribute(gemm_h<true>,
                         cudaFuncAttributeMaxDynamicSharedMemorySize, smem_gemm);
    cudaFuncSetAttribute(gemm_h<false>,
                         cudaFuncAttributeMaxDynamicSharedMemorySize, smem_gemm);

    conv_x<<<(M_TOT * DIM / 4 + 255) / 256, 256>>>(x);
    conv_mask<<<(BN * PSQ / 4 + 255) / 256, 256>>>(mask);
    conv_w<<<128, 256>>>(w_qkv, w_proj);
    bias_prep<<<WT * 8, 256>>>(bias_table);
    gemm_h<true><<<dim3(9, M_TOT / 128), 256, smem_gemm>>>(nullptr, nullptr);
    attn_h<<<BN * HEADS, 288>>>(0);
    gemm_h<false><<<dim3(3, M_TOT / 128), 256, smem_gemm>>>(b_proj, out);
}